// round 12
// baseline (speedup 1.0000x reference)
#include <cuda_runtime.h>
#include <cuda_bf16.h>
#include <math.h>
#include <stdint.h>

#define BB 2
#define TT 2048
#define CC 768
#define NH 12
#define HD 64
#define MQ (BB*TT)   // 4096

// Scratch (allocation-free rule: __device__ globals)
__device__ float g_q[BB*NH*TT*HD];
__device__ __nv_bfloat16 g_kh[BB*NH*TT*HD], g_kl[BB*NH*TT*HD];
__device__ __nv_bfloat16 g_vh[BB*NH*TT*HD], g_vl[BB*NH*TT*HD];
__device__ __nv_bfloat16 g_ath[(size_t)BB*TT*CC], g_atl[(size_t)BB*TT*CC];
__device__ __nv_bfloat16 gXh[MQ*CC],     gXl[MQ*CC];
__device__ __nv_bfloat16 gWah[3*CC*CC],  gWal[3*CC*CC];
__device__ __nv_bfloat16 gWph[CC*CC],    gWpl[CC*CC];

// ---------------------------------------------------------------------------
// helpers
// ---------------------------------------------------------------------------
__device__ __forceinline__ void mma_bf16(float* d, const uint32_t* a,
                                         const uint32_t* b) {
    asm volatile(
        "mma.sync.aligned.m16n8k16.row.col.f32.bf16.bf16.f32 "
        "{%0,%1,%2,%3}, {%4,%5,%6,%7}, {%8,%9}, {%0,%1,%2,%3};"
        : "+f"(d[0]), "+f"(d[1]), "+f"(d[2]), "+f"(d[3])
        : "r"(a[0]), "r"(a[1]), "r"(a[2]), "r"(a[3]), "r"(b[0]), "r"(b[1]));
}

__device__ __forceinline__ void ldm_x4(uint32_t* r, const void* p) {
    uint32_t addr = (uint32_t)__cvta_generic_to_shared(p);
    asm volatile("ldmatrix.sync.aligned.m8n8.x4.shared.b16 {%0,%1,%2,%3}, [%4];"
                 : "=r"(r[0]), "=r"(r[1]), "=r"(r[2]), "=r"(r[3]) : "r"(addr));
}

__device__ __forceinline__ void ldm_x4_trans(uint32_t* r, const void* p) {
    uint32_t addr = (uint32_t)__cvta_generic_to_shared(p);
    asm volatile("ldmatrix.sync.aligned.m8n8.x4.trans.shared.b16 {%0,%1,%2,%3}, [%4];"
                 : "=r"(r[0]), "=r"(r[1]), "=r"(r[2]), "=r"(r[3]) : "r"(addr));
}

__device__ __forceinline__ float ex2f(float x) {
    float y;
    asm("ex2.approx.f32 %0, %1;" : "=f"(y) : "f"(x));
    return y;
}

__device__ __forceinline__ void cp16(void* smem, const void* gmem) {
    uint32_t a = (uint32_t)__cvta_generic_to_shared(smem);
    asm volatile("cp.async.ca.shared.global [%0], [%1], 16;" :: "r"(a), "l"(gmem));
}
__device__ __forceinline__ void cp16cg(void* smem, const void* gmem) {
    uint32_t a = (uint32_t)__cvta_generic_to_shared(smem);
    asm volatile("cp.async.cg.shared.global [%0], [%1], 16;" :: "r"(a), "l"(gmem));
}
#define CP_COMMIT() asm volatile("cp.async.commit_group;" ::: "memory")
#define CP_WAIT0()  asm volatile("cp.async.wait_group 0;" ::: "memory")
#define CP_WAIT1()  asm volatile("cp.async.wait_group 1;" ::: "memory")

// Split (x,y) into packed bf16x2 hi and lo (x in low half)
__device__ __forceinline__ void split2(float x, float y, uint32_t& hi, uint32_t& lo) {
    __nv_bfloat16 hx = __float2bfloat16_rn(x);
    __nv_bfloat16 hy = __float2bfloat16_rn(y);
    __nv_bfloat162 h2(hx, hy);
    __nv_bfloat162 l2(__float2bfloat16_rn(x - __bfloat162float(hx)),
                      __float2bfloat16_rn(y - __bfloat162float(hy)));
    hi = *(uint32_t*)&h2;
    lo = *(uint32_t*)&l2;
}

// ---------------------------------------------------------------------------
// Pre-pass: split fp32 -> bf16 hi/lo
// ---------------------------------------------------------------------------
__global__ __launch_bounds__(256) void split_pass(const float* __restrict__ src,
                                                  __nv_bfloat16* __restrict__ dh,
                                                  __nv_bfloat16* __restrict__ dl,
                                                  int n4) {
    int i = blockIdx.x * 256 + threadIdx.x;
    if (i < n4) {
        float4 v = ((const float4*)src)[i];
        uint32_t h0, l0, h1, l1;
        split2(v.x, v.y, h0, l0);
        split2(v.z, v.w, h1, l1);
        ((uint32_t*)dh)[i * 2]     = h0;
        ((uint32_t*)dh)[i * 2 + 1] = h1;
        ((uint32_t*)dl)[i * 2]     = l0;
        ((uint32_t*)dl)[i * 2 + 1] = l1;
    }
}

// ---------------------------------------------------------------------------
// HMMA GEMM, cp.async.cg double-buffered, 128x128 tile.
// Fill path: gmem -> smem direct (L1 bypass), no LDG/STS register staging.
// ---------------------------------------------------------------------------
#define SMP 24
#define NCH (CC / 16)   // 48 chunks

#define TC_GEMM_BODY(AH, AL, BH, BL)                                          \
    __shared__ __nv_bfloat16 sAh[2][128 * SMP], sAl[2][128 * SMP];            \
    __shared__ __nv_bfloat16 sBh[2][128 * SMP], sBl[2][128 * SMP];            \
    const int tid = threadIdx.x;                                              \
    const int wid = tid >> 5, lane = tid & 31;                                \
    const int m0 = blockIdx.y * 128, n0 = blockIdx.x * 128;                   \
    const int wm = (wid & 1) * 64;                                            \
    const int wn = (wid >> 1) * 32;                                           \
    float acc[4][4][4];                                                       \
    _Pragma("unroll")                                                         \
    for (int i = 0; i < 4; i++)                                               \
        _Pragma("unroll")                                                     \
        for (int j = 0; j < 4; j++)                                           \
            _Pragma("unroll")                                                 \
            for (int e = 0; e < 4; e++) acc[i][j][e] = 0.0f;                  \
    const int lrow = tid >> 1;                                                \
    const int lseg = (tid & 1) * 8;                                           \
    const __nv_bfloat16* pah = (AH) + (size_t)(m0 + lrow) * CC + lseg;        \
    const __nv_bfloat16* pal = (AL) + (size_t)(m0 + lrow) * CC + lseg;        \
    const __nv_bfloat16* pbh = (BH) + (size_t)(n0 + lrow) * CC + lseg;        \
    const __nv_bfloat16* pbl = (BL) + (size_t)(n0 + lrow) * CC + lseg;        \
    const int soff = lrow * SMP + lseg;                                       \
    cp16cg(&sAh[0][soff], pah);                                               \
    cp16cg(&sAl[0][soff], pal);                                               \
    cp16cg(&sBh[0][soff], pbh);                                               \
    cp16cg(&sBl[0][soff], pbl);                                               \
    CP_COMMIT();                                                              \
    _Pragma("unroll 1")                                                       \
    for (int c = 0; c < NCH; c++) {                                           \
        const int cur = c & 1, nxt = cur ^ 1;                                 \
        if (c + 1 < NCH) {                                                    \
            int ko = (c + 1) * 16;                                            \
            cp16cg(&sAh[nxt][soff], pah + ko);                                \
            cp16cg(&sAl[nxt][soff], pal + ko);                                \
            cp16cg(&sBh[nxt][soff], pbh + ko);                                \
            cp16cg(&sBl[nxt][soff], pbl + ko);                                \
            CP_COMMIT();                                                      \
            CP_WAIT1();                                                       \
        } else {                                                              \
            CP_WAIT0();                                                       \
        }                                                                     \
        __syncthreads();                                                      \
        uint32_t fbh[4][2], fbl[4][2];                                        \
        {                                                                     \
            int br = (lane & 7) + ((lane >> 1) & 8);                          \
            int bc = lane & 8;                                                \
            _Pragma("unroll")                                                 \
            for (int ntp = 0; ntp < 2; ntp++) {                               \
                uint32_t t4[4];                                               \
                ldm_x4(t4, &sBh[cur][(wn + ntp * 16 + br) * SMP + bc]);       \
                fbh[2 * ntp][0] = t4[0]; fbh[2 * ntp][1] = t4[1];             \
                fbh[2 * ntp + 1][0] = t4[2]; fbh[2 * ntp + 1][1] = t4[3];     \
                ldm_x4(t4, &sBl[cur][(wn + ntp * 16 + br) * SMP + bc]);       \
                fbl[2 * ntp][0] = t4[0]; fbl[2 * ntp][1] = t4[1];             \
                fbl[2 * ntp + 1][0] = t4[2]; fbl[2 * ntp + 1][1] = t4[3];     \
            }                                                                 \
        }                                                                     \
        {                                                                     \
            int mat = lane >> 3, rr = lane & 7;                               \
            int arow_off = (mat & 1) * 8 + rr;                                \
            int acol = (mat >> 1) * 8;                                        \
            _Pragma("unroll")                                                 \
            for (int mt = 0; mt < 4; mt++) {                                  \
                uint32_t fah[4], fal[4];                                      \
                int arow = wm + mt * 16 + arow_off;                           \
                ldm_x4(fah, &sAh[cur][arow * SMP + acol]);                    \
                ldm_x4(fal, &sAl[cur][arow * SMP + acol]);                    \
                _Pragma("unroll")                                             \
                for (int nt = 0; nt < 4; nt++) {                              \
                    mma_bf16(acc[mt][nt], fah, fbh[nt]);                      \
                    mma_bf16(acc[mt][nt], fah, fbl[nt]);                      \
                    mma_bf16(acc[mt][nt], fal, fbh[nt]);                      \
                }                                                             \
            }                                                                 \
        }                                                                     \
        __syncthreads();                                                      \
    }

// GEMM1: qkv. Q -> fp32 g_q; K,V -> bf16 hi/lo, all in [B,H,T,D]
__global__ __launch_bounds__(256) void qkv_gemm() {
    TC_GEMM_BODY(gXh, gXl, gWah, gWal)
    #pragma unroll
    for (int mt = 0; mt < 4; mt++) {
        #pragma unroll
        for (int nt = 0; nt < 4; nt++) {
            int n = n0 + wn + nt * 8 + (lane & 3) * 2;
            int sec = n / CC;               // 0=q 1=k 2=v
            int c2 = n - sec * CC;
            int h = c2 >> 6, d = c2 & 63;
            #pragma unroll
            for (int half = 0; half < 2; half++) {
                int m = m0 + wm + mt * 16 + (lane >> 2) + half * 8;
                int b = m >> 11, t = m & 2047;
                size_t idx = (size_t)((b * NH + h) * TT + t) * HD + d;
                float v0 = acc[mt][nt][half * 2 + 0];
                float v1 = acc[mt][nt][half * 2 + 1];
                if (sec == 0) {
                    *(float2*)&g_q[idx] = make_float2(v0, v1);
                } else {
                    uint32_t hh, ll;
                    split2(v0, v1, hh, ll);
                    if (sec == 1) {
                        *(uint32_t*)&g_kh[idx] = hh;
                        *(uint32_t*)&g_kl[idx] = ll;
                    } else {
                        *(uint32_t*)&g_vh[idx] = hh;
                        *(uint32_t*)&g_vl[idx] = ll;
                    }
                }
            }
        }
    }
}

// ---------------------------------------------------------------------------
// proj GEMM: 64x128 tile, cp.async.cg double-buffered.
// ---------------------------------------------------------------------------
__global__ __launch_bounds__(256) void proj_gemm(float* __restrict__ out) {
    __shared__ __nv_bfloat16 sAh[2][64 * SMP], sAl[2][64 * SMP];
    __shared__ __nv_bfloat16 sBh[2][128 * SMP], sBl[2][128 * SMP];
    const int tid = threadIdx.x;
    const int wid = tid >> 5, lane = tid & 31;
    const int m0 = blockIdx.y * 64, n0 = blockIdx.x * 128;
    const int wm = (wid & 1) * 32;
    const int wn = (wid >> 1) * 32;
    float acc[2][4][4];
    #pragma unroll
    for (int i = 0; i < 2; i++)
        #pragma unroll
        for (int j = 0; j < 4; j++)
            #pragma unroll
            for (int e = 0; e < 4; e++) acc[i][j][e] = 0.0f;
    const int lrow = tid >> 1;
    const int lseg = (tid & 1) * 8;
    const __nv_bfloat16* pah = g_ath + (size_t)(m0 + (lrow & 63)) * CC + lseg;
    const __nv_bfloat16* pal = g_atl + (size_t)(m0 + (lrow & 63)) * CC + lseg;
    const __nv_bfloat16* pbh = gWph + (size_t)(n0 + lrow) * CC + lseg;
    const __nv_bfloat16* pbl = gWpl + (size_t)(n0 + lrow) * CC + lseg;
    const bool doA = (lrow < 64);
    const int soff = lrow * SMP + lseg;
    cp16cg(&sBh[0][soff], pbh);
    cp16cg(&sBl[0][soff], pbl);
    if (doA) {
        cp16cg(&sAh[0][soff], pah);
        cp16cg(&sAl[0][soff], pal);
    }
    CP_COMMIT();
    #pragma unroll 1
    for (int c = 0; c < NCH; c++) {
        const int cur = c & 1, nxt = cur ^ 1;
        if (c + 1 < NCH) {
            int ko = (c + 1) * 16;
            cp16cg(&sBh[nxt][soff], pbh + ko);
            cp16cg(&sBl[nxt][soff], pbl + ko);
            if (doA) {
                cp16cg(&sAh[nxt][soff], pah + ko);
                cp16cg(&sAl[nxt][soff], pal + ko);
            }
            CP_COMMIT();
            CP_WAIT1();
        } else {
            CP_WAIT0();
        }
        __syncthreads();
        uint32_t fbh[4][2], fbl[4][2];
        {
            int br = (lane & 7) + ((lane >> 1) & 8);
            int bc = lane & 8;
            #pragma unroll
            for (int ntp = 0; ntp < 2; ntp++) {
                uint32_t t4[4];
                ldm_x4(t4, &sBh[cur][(wn + ntp * 16 + br) * SMP + bc]);
                fbh[2 * ntp][0] = t4[0]; fbh[2 * ntp][1] = t4[1];
                fbh[2 * ntp + 1][0] = t4[2]; fbh[2 * ntp + 1][1] = t4[3];
                ldm_x4(t4, &sBl[cur][(wn + ntp * 16 + br) * SMP + bc]);
                fbl[2 * ntp][0] = t4[0]; fbl[2 * ntp][1] = t4[1];
                fbl[2 * ntp + 1][0] = t4[2]; fbl[2 * ntp + 1][1] = t4[3];
            }
        }
        {
            int mat = lane >> 3, rr = lane & 7;
            int arow_off = (mat & 1) * 8 + rr;
            int acol = (mat >> 1) * 8;
            #pragma unroll
            for (int mt = 0; mt < 2; mt++) {
                uint32_t fah[4], fal[4];
                int arow = wm + mt * 16 + arow_off;
                ldm_x4(fah, &sAh[cur][arow * SMP + acol]);
                ldm_x4(fal, &sAl[cur][arow * SMP + acol]);
                #pragma unroll
                for (int nt = 0; nt < 4; nt++) {
                    mma_bf16(acc[mt][nt], fah, fbh[nt]);
                    mma_bf16(acc[mt][nt], fah, fbl[nt]);
                    mma_bf16(acc[mt][nt], fal, fbh[nt]);
                }
            }
        }
        __syncthreads();
    }
    #pragma unroll
    for (int mt = 0; mt < 2; mt++) {
        #pragma unroll
        for (int nt = 0; nt < 4; nt++) {
            int n = n0 + wn + nt * 8 + (lane & 3) * 2;
            #pragma unroll
            for (int half = 0; half < 2; half++) {
                int m = m0 + wm + mt * 16 + (lane >> 2) + half * 8;
                float2 v2 = make_float2(acc[mt][nt][half * 2 + 0],
                                        acc[mt][nt][half * 2 + 1]);
                *(float2*)&out[(size_t)m * CC + n] = v2;
            }
        }
    }
}

// ---------------------------------------------------------------------------
// HMMA flash attention (unchanged from R11): Bq=64, Bk=64, cp.async
// split-phase pipeline, base-2 softmax.
// ---------------------------------------------------------------------------
#define ATP 72

__global__ __launch_bounds__(128, 3) void attn_kernel() {
    __shared__ __nv_bfloat16 sKh[64 * ATP], sKl[64 * ATP];
    __shared__ __nv_bfloat16 sVh[64 * ATP], sVl[64 * ATP];

    const int qt = gridDim.x - 1 - blockIdx.x;   // heavy blocks first
    const int bh = blockIdx.y;
    const int q0 = qt * 64;
    const int tid = threadIdx.x;
    const int warp = tid >> 5, lane = tid & 31;
    const size_t base = (size_t)bh * TT * HD;
    const float* qp = g_q + base;

    const int r = lane >> 2;
    const int c2 = (lane & 3) * 2;
    const float QS = 0.125f * 1.44269504088896f;   // 1/sqrt(64) * log2(e)

    const int frow = tid >> 1;          // 0..63
    const int fcb  = (tid & 1) * 32;    // col half

    // ---- prologue: start K(0) and V(0) streams ----
    {
        size_t g = base + (size_t)frow * HD + fcb;
        #pragma unroll
        for (int u = 0; u < 4; u++) {
            cp16(&sKh[frow * ATP + fcb + u * 8], &g_kh[g + u * 8]);
            cp16(&sKl[frow * ATP + fcb + u * 8], &g_kl[g + u * 8]);
        }
        CP_COMMIT();
        #pragma unroll
        for (int u = 0; u < 4; u++) {
            cp16(&sVh[frow * ATP + fcb + u * 8], &g_vh[g + u * 8]);
            cp16(&sVl[frow * ATP + fcb + u * 8], &g_vl[g + u * 8]);
        }
        CP_COMMIT();
    }

    // Q fragments (A-layout, 4 k-chunks over HD=64), hi/lo, from gmem
    uint32_t qfh[4][4], qfl[4][4];
    #pragma unroll
    for (int kc = 0; kc < 4; kc++) {
        #pragma unroll
        for (int e = 0; e < 4; e++) {
            int row = q0 + warp * 16 + r + ((e & 1) ? 8 : 0);
            int col = kc * 16 + c2 + ((e & 2) ? 8 : 0);
            float2 v = *(const float2*)&qp[(size_t)row * HD + col];
            split2(v.x * QS, v.y * QS, qfh[kc][e], qfl[kc][e]);
        }
    }

    float mi[2] = {-1e30f, -1e30f};
    float li[2] = {0.0f, 0.0f};
    float o[8][4];
    #pragma unroll
    for (int nt = 0; nt < 8; nt++)
        #pragma unroll
        for (int e = 0; e < 4; e++) o[nt][e] = 0.0f;

    CP_WAIT1();          // K(0) ready (V(0) may still be in flight)
    __syncthreads();

    for (int kt = 0; kt <= qt; kt++) {
        const int k0 = kt * 64;

        // ---- S = Q @ K^T  (K(kt) resident) ----
        float s[8][4];
        #pragma unroll
        for (int nt = 0; nt < 8; nt++)
            #pragma unroll
            for (int e = 0; e < 4; e++) s[nt][e] = 0.0f;

        {
            int br = (lane & 7) + ((lane >> 1) & 8);
            int bc = lane & 8;
            #pragma unroll
            for (int ntp = 0; ntp < 4; ntp++) {
                #pragma unroll
                for (int kc = 0; kc < 4; kc++) {
                    uint32_t kh4[4], kl4[4];
                    ldm_x4(kh4, &sKh[(ntp * 16 + br) * ATP + kc * 16 + bc]);
                    ldm_x4(kl4, &sKl[(ntp * 16 + br) * ATP + kc * 16 + bc]);
                    mma_bf16(s[2 * ntp],     qfh[kc], kh4);
                    mma_bf16(s[2 * ntp],     qfh[kc], kl4);
                    mma_bf16(s[2 * ntp],     qfl[kc], kh4);
                    mma_bf16(s[2 * ntp + 1], qfh[kc], kh4 + 2);
                    mma_bf16(s[2 * ntp + 1], qfh[kc], kl4 + 2);
                    mma_bf16(s[2 * ntp + 1], qfl[kc], kh4 + 2);
                }
            }
        }
        __syncthreads();   // all warps done reading K(kt)

        // ---- issue K(kt+1) stream (overlaps softmax) ----
        if (kt < qt) {
            size_t g = base + (size_t)(k0 + 64 + frow) * HD + fcb;
            #pragma unroll
            for (int u = 0; u < 4; u++) {
                cp16(&sKh[frow * ATP + fcb + u * 8], &g_kh[g + u * 8]);
                cp16(&sKl[frow * ATP + fcb + u * 8], &g_kl[g + u * 8]);
            }
        }
        CP_COMMIT();

        // ---- causal mask on diagonal tile ----
        if (kt == qt) {
            const int row0 = q0 + warp * 16 + r;
            #pragma unroll
            for (int nt = 0; nt < 8; nt++) {
                int colb = k0 + nt * 8 + c2;
                if (colb     > row0)     s[nt][0] = -1e30f;
                if (colb + 1 > row0)     s[nt][1] = -1e30f;
                if (colb     > row0 + 8) s[nt][2] = -1e30f;
                if (colb + 1 > row0 + 8) s[nt][3] = -1e30f;
            }
        }

        // ---- online softmax (base-2) ----
        #pragma unroll
        for (int h = 0; h < 2; h++) {
            float m = -1e30f;
            #pragma unroll
            for (int nt = 0; nt < 8; nt++)
                m = fmaxf(m, fmaxf(s[nt][h * 2], s[nt][h * 2 + 1]));
            m = fmaxf(m, __shfl_xor_sync(0xffffffffu, m, 1));
            m = fmaxf(m, __shfl_xor_sync(0xffffffffu, m, 2));
            float mnew = fmaxf(mi[h], m);
            float alpha = ex2f(mi[h] - mnew);
            float sum = 0.0f;
            #pragma unroll
            for (int nt = 0; nt < 8; nt++) {
                s[nt][h * 2]     = ex2f(s[nt][h * 2] - mnew);
                s[nt][h * 2 + 1] = ex2f(s[nt][h * 2 + 1] - mnew);
                sum += s[nt][h * 2] + s[nt][h * 2 + 1];
            }
            sum += __shfl_xor_sync(0xffffffffu, sum, 1);
            sum += __shfl_xor_sync(0xffffffffu, sum, 2);
            li[h] = li[h] * alpha + sum;
            mi[h] = mnew;
            #pragma unroll
            for (int nt = 0; nt < 8; nt++) {
                o[nt][h * 2]     *= alpha;
                o[nt][h * 2 + 1] *= alpha;
            }
        }

        // ---- P to A-fragments, hi/lo split (still overlapping K stream) ----
        uint32_t pfh[4][4], pfl[4][4];
        #pragma unroll
        for (int kc = 0; kc < 4; kc++) {
            split2(s[2 * kc][0],     s[2 * kc][1],     pfh[kc][0], pfl[kc][0]);
            split2(s[2 * kc][2],     s[2 * kc][3],     pfh[kc][1], pfl[kc][1]);
            split2(s[2 * kc + 1][0], s[2 * kc + 1][1], pfh[kc][2], pfl[kc][2]);
            split2(s[2 * kc + 1][2], s[2 * kc + 1][3], pfh[kc][3], pfl[kc][3]);
        }

        CP_WAIT1();        // V(kt) ready (K(kt+1) may still be in flight)
        __syncthreads();

        // ---- O += P @ V ----
        {
            const int vr = lane & 15;
            const int vc = (lane >> 4) & 1;
            #pragma unroll
            for (int ntp = 0; ntp < 4; ntp++) {
                #pragma unroll
                for (int kc = 0; kc < 4; kc++) {
                    uint32_t vh4[4], vl4[4];
                    ldm_x4_trans(vh4, &sVh[(kc * 16 + vr) * ATP + (2 * ntp + vc) * 8]);
                    ldm_x4_trans(vl4, &sVl[(kc * 16 + vr) * ATP + (2 * ntp + vc) * 8]);
                    mma_bf16(o[2 * ntp],     pfh[kc], vh4);
                    mma_bf16(o[2 * ntp],     pfh[kc], vl4);
                    mma_bf16(o[2 * ntp],     pfl[kc], vh4);
                    mma_bf16(o[2 * ntp + 1], pfh[kc], vh4 + 2);
                    mma_bf16(o[2 * ntp + 1], pfh[kc], vl4 + 2);
                    mma_bf16(o[2 * ntp + 1], pfl[kc], vh4 + 2);
                }
            }
        }
        __syncthreads();   // all warps done reading V(kt)

        // ---- issue V(kt+1) stream (overlaps next S-MMA) ----
        if (kt < qt) {
            size_t g = base + (size_t)(k0 + 64 + frow) * HD + fcb;
            #pragma unroll
            for (int u = 0; u < 4; u++) {
                cp16(&sVh[frow * ATP + fcb + u * 8], &g_vh[g + u * 8]);
                cp16(&sVl[frow * ATP + fcb + u * 8], &g_vl[g + u * 8]);
            }
        }
        CP_COMMIT();

        CP_WAIT1();        // K(kt+1) ready (V(kt+1) may still be in flight)
        __syncthreads();
    }

    // ---- epilogue: normalize, split, write bf16 hi/lo [B,T,C] ----
    const int b = bh / NH, head = bh % NH;
    #pragma unroll
    for (int h = 0; h < 2; h++) {
        float inv = 1.0f / li[h];
        int row = q0 + warp * 16 + r + h * 8;
        size_t doff = (size_t)(b * TT + row) * CC + head * HD;
        #pragma unroll
        for (int nt = 0; nt < 8; nt++) {
            uint32_t hh, ll;
            split2(o[nt][h * 2] * inv, o[nt][h * 2 + 1] * inv, hh, ll);
            *(uint32_t*)&g_ath[doff + nt * 8 + c2] = hh;
            *(uint32_t*)&g_atl[doff + nt * 8 + c2] = ll;
        }
    }
}

// ---------------------------------------------------------------------------
extern "C" void kernel_launch(void* const* d_in, const int* in_sizes, int n_in,
                              void* d_out, int out_size) {
    const float* x  = (const float*)d_in[0];   // [2,2048,768]
    const float* Wa = (const float*)d_in[1];   // [2304,768]
    const float* Wp = (const float*)d_in[2];   // [768,768]
    float* out = (float*)d_out;                // [2,2048,768]

    __nv_bfloat16 *xh, *xl, *wah, *wal, *wph, *wpl;
    cudaGetSymbolAddress((void**)&xh,  gXh);
    cudaGetSymbolAddress((void**)&xl,  gXl);
    cudaGetSymbolAddress((void**)&wah, gWah);
    cudaGetSymbolAddress((void**)&wal, gWal);
    cudaGetSymbolAddress((void**)&wph, gWph);
    cudaGetSymbolAddress((void**)&wpl, gWpl);

    split_pass<<<(MQ * CC / 4 + 255) / 256, 256>>>(x, xh, xl, MQ * CC / 4);
    split_pass<<<(3 * CC * CC / 4 + 255) / 256, 256>>>(Wa, wah, wal, 3 * CC * CC / 4);
    split_pass<<<(CC * CC / 4 + 255) / 256, 256>>>(Wp, wph, wpl, CC * CC / 4);

    // QKV: M=4096 (32 tiles), N=2304 (18 tiles)
    qkv_gemm<<<dim3(18, 32), 256>>>();

    // Attention: 32 q-tiles (Bq=64) x 24 (b,h)
    attn_kernel<<<dim3(32, 24), 128>>>();

    // Proj: M=4096 (64 tiles of 64), N=768 (6 tiles of 128)
    proj_gemm<<<dim3(6, 64), 256>>>(out);
}

// round 13
// speedup vs baseline: 1.0351x; 1.0351x over previous
#include <cuda_runtime.h>
#include <cuda_bf16.h>
#include <math.h>
#include <stdint.h>

#define BB 2
#define TT 2048
#define CC 768
#define NH 12
#define HD 64
#define MQ (BB*TT)   // 4096

// Scratch (allocation-free rule: __device__ globals)
__device__ float g_q[BB*NH*TT*HD];
__device__ __nv_bfloat16 g_kh[BB*NH*TT*HD], g_kl[BB*NH*TT*HD];
__device__ __nv_bfloat16 g_vh[BB*NH*TT*HD], g_vl[BB*NH*TT*HD];
__device__ __nv_bfloat16 g_ath[(size_t)BB*TT*CC], g_atl[(size_t)BB*TT*CC];
__device__ __nv_bfloat16 gXh[MQ*CC],     gXl[MQ*CC];
__device__ __nv_bfloat16 gWah[3*CC*CC],  gWal[3*CC*CC];
__device__ __nv_bfloat16 gWph[CC*CC],    gWpl[CC*CC];

// ---------------------------------------------------------------------------
// helpers
// ---------------------------------------------------------------------------
__device__ __forceinline__ void mma_bf16(float* d, const uint32_t* a,
                                         const uint32_t* b) {
    asm volatile(
        "mma.sync.aligned.m16n8k16.row.col.f32.bf16.bf16.f32 "
        "{%0,%1,%2,%3}, {%4,%5,%6,%7}, {%8,%9}, {%0,%1,%2,%3};"
        : "+f"(d[0]), "+f"(d[1]), "+f"(d[2]), "+f"(d[3])
        : "r"(a[0]), "r"(a[1]), "r"(a[2]), "r"(a[3]), "r"(b[0]), "r"(b[1]));
}

__device__ __forceinline__ void ldm_x4(uint32_t* r, const void* p) {
    uint32_t addr = (uint32_t)__cvta_generic_to_shared(p);
    asm volatile("ldmatrix.sync.aligned.m8n8.x4.shared.b16 {%0,%1,%2,%3}, [%4];"
                 : "=r"(r[0]), "=r"(r[1]), "=r"(r[2]), "=r"(r[3]) : "r"(addr));
}

__device__ __forceinline__ void ldm_x4_trans(uint32_t* r, const void* p) {
    uint32_t addr = (uint32_t)__cvta_generic_to_shared(p);
    asm volatile("ldmatrix.sync.aligned.m8n8.x4.trans.shared.b16 {%0,%1,%2,%3}, [%4];"
                 : "=r"(r[0]), "=r"(r[1]), "=r"(r[2]), "=r"(r[3]) : "r"(addr));
}

__device__ __forceinline__ float ex2f(float x) {
    float y;
    asm("ex2.approx.f32 %0, %1;" : "=f"(y) : "f"(x));
    return y;
}

__device__ __forceinline__ void cp16(void* smem, const void* gmem) {
    uint32_t a = (uint32_t)__cvta_generic_to_shared(smem);
    asm volatile("cp.async.ca.shared.global [%0], [%1], 16;" :: "r"(a), "l"(gmem));
}
__device__ __forceinline__ void cp16cg(void* smem, const void* gmem) {
    uint32_t a = (uint32_t)__cvta_generic_to_shared(smem);
    asm volatile("cp.async.cg.shared.global [%0], [%1], 16;" :: "r"(a), "l"(gmem));
}
#define CP_COMMIT() asm volatile("cp.async.commit_group;" ::: "memory")
#define CP_WAIT0()  asm volatile("cp.async.wait_group 0;" ::: "memory")
#define CP_WAIT1()  asm volatile("cp.async.wait_group 1;" ::: "memory")

// Split (x,y) into packed bf16x2 hi and lo (x in low half)
__device__ __forceinline__ void split2(float x, float y, uint32_t& hi, uint32_t& lo) {
    __nv_bfloat16 hx = __float2bfloat16_rn(x);
    __nv_bfloat16 hy = __float2bfloat16_rn(y);
    __nv_bfloat162 h2(hx, hy);
    __nv_bfloat162 l2(__float2bfloat16_rn(x - __bfloat162float(hx)),
                      __float2bfloat16_rn(y - __bfloat162float(hy)));
    hi = *(uint32_t*)&h2;
    lo = *(uint32_t*)&l2;
}

// ---------------------------------------------------------------------------
// Pre-pass: split fp32 -> bf16 hi/lo
// ---------------------------------------------------------------------------
__global__ __launch_bounds__(256) void split_pass(const float* __restrict__ src,
                                                  __nv_bfloat16* __restrict__ dh,
                                                  __nv_bfloat16* __restrict__ dl,
                                                  int n4) {
    int i = blockIdx.x * 256 + threadIdx.x;
    if (i < n4) {
        float4 v = ((const float4*)src)[i];
        uint32_t h0, l0, h1, l1;
        split2(v.x, v.y, h0, l0);
        split2(v.z, v.w, h1, l1);
        ((uint32_t*)dh)[i * 2]     = h0;
        ((uint32_t*)dh)[i * 2 + 1] = h1;
        ((uint32_t*)dl)[i * 2]     = l0;
        ((uint32_t*)dl)[i * 2 + 1] = l1;
    }
}

// ---------------------------------------------------------------------------
// qkv GEMM: 128x128 tile, REGISTER-PREFETCH double-buffered smem (best
// measured variant, R9): LDG->reg overlap hides gmem latency under MMA.
// ---------------------------------------------------------------------------
#define SMP 24
#define NCH (CC / 16)   // 48 chunks

__global__ __launch_bounds__(256) void qkv_gemm() {
    __shared__ __nv_bfloat16 sAh[2][128 * SMP], sAl[2][128 * SMP];
    __shared__ __nv_bfloat16 sBh[2][128 * SMP], sBl[2][128 * SMP];
    const int tid = threadIdx.x;
    const int wid = tid >> 5, lane = tid & 31;
    const int m0 = blockIdx.y * 128, n0 = blockIdx.x * 128;
    const int wm = (wid & 1) * 64;
    const int wn = (wid >> 1) * 32;
    float acc[4][4][4];
    #pragma unroll
    for (int i = 0; i < 4; i++)
        #pragma unroll
        for (int j = 0; j < 4; j++)
            #pragma unroll
            for (int e = 0; e < 4; e++) acc[i][j][e] = 0.0f;
    const int lrow = tid >> 1;
    const int lseg = (tid & 1) * 8;
    const __nv_bfloat16* pah = gXh  + (size_t)(m0 + lrow) * CC + lseg;
    const __nv_bfloat16* pal = gXl  + (size_t)(m0 + lrow) * CC + lseg;
    const __nv_bfloat16* pbh = gWah + (size_t)(n0 + lrow) * CC + lseg;
    const __nv_bfloat16* pbl = gWal + (size_t)(n0 + lrow) * CC + lseg;
    const int soff = lrow * SMP + lseg;
    {
        uint4 a0 = *(const uint4*)pah;
        uint4 a1 = *(const uint4*)pal;
        uint4 b0 = *(const uint4*)pbh;
        uint4 b1 = *(const uint4*)pbl;
        *(uint4*)&sAh[0][soff] = a0;
        *(uint4*)&sAl[0][soff] = a1;
        *(uint4*)&sBh[0][soff] = b0;
        *(uint4*)&sBl[0][soff] = b1;
    }
    __syncthreads();
    #pragma unroll 1
    for (int c = 0; c < NCH; c++) {
        const int cur = c & 1, nxt = cur ^ 1;
        uint4 rah, ral, rbh, rbl;
        if (c + 1 < NCH) {
            int ko = (c + 1) * 16;
            rah = *(const uint4*)(pah + ko);
            ral = *(const uint4*)(pal + ko);
            rbh = *(const uint4*)(pbh + ko);
            rbl = *(const uint4*)(pbl + ko);
        }
        uint32_t fbh[4][2], fbl[4][2];
        {
            int br = (lane & 7) + ((lane >> 1) & 8);
            int bc = lane & 8;
            #pragma unroll
            for (int ntp = 0; ntp < 2; ntp++) {
                uint32_t t4[4];
                ldm_x4(t4, &sBh[cur][(wn + ntp * 16 + br) * SMP + bc]);
                fbh[2 * ntp][0] = t4[0]; fbh[2 * ntp][1] = t4[1];
                fbh[2 * ntp + 1][0] = t4[2]; fbh[2 * ntp + 1][1] = t4[3];
                ldm_x4(t4, &sBl[cur][(wn + ntp * 16 + br) * SMP + bc]);
                fbl[2 * ntp][0] = t4[0]; fbl[2 * ntp][1] = t4[1];
                fbl[2 * ntp + 1][0] = t4[2]; fbl[2 * ntp + 1][1] = t4[3];
            }
        }
        {
            int mat = lane >> 3, rr = lane & 7;
            int arow_off = (mat & 1) * 8 + rr;
            int acol = (mat >> 1) * 8;
            #pragma unroll
            for (int mt = 0; mt < 4; mt++) {
                uint32_t fah[4], fal[4];
                int arow = wm + mt * 16 + arow_off;
                ldm_x4(fah, &sAh[cur][arow * SMP + acol]);
                ldm_x4(fal, &sAl[cur][arow * SMP + acol]);
                #pragma unroll
                for (int nt = 0; nt < 4; nt++) {
                    mma_bf16(acc[mt][nt], fah, fbh[nt]);
                    mma_bf16(acc[mt][nt], fah, fbl[nt]);
                    mma_bf16(acc[mt][nt], fal, fbh[nt]);
                }
            }
        }
        if (c + 1 < NCH) {
            *(uint4*)&sAh[nxt][soff] = rah;
            *(uint4*)&sAl[nxt][soff] = ral;
            *(uint4*)&sBh[nxt][soff] = rbh;
            *(uint4*)&sBl[nxt][soff] = rbl;
        }
        __syncthreads();
    }
    // epilogue: Q -> fp32 g_q; K,V -> bf16 hi/lo, all [B,H,T,D]
    #pragma unroll
    for (int mt = 0; mt < 4; mt++) {
        #pragma unroll
        for (int nt = 0; nt < 4; nt++) {
            int n = n0 + wn + nt * 8 + (lane & 3) * 2;
            int sec = n / CC;               // 0=q 1=k 2=v
            int c2 = n - sec * CC;
            int h = c2 >> 6, d = c2 & 63;
            #pragma unroll
            for (int half = 0; half < 2; half++) {
                int m = m0 + wm + mt * 16 + (lane >> 2) + half * 8;
                int b = m >> 11, t = m & 2047;
                size_t idx = (size_t)((b * NH + h) * TT + t) * HD + d;
                float v0 = acc[mt][nt][half * 2 + 0];
                float v1 = acc[mt][nt][half * 2 + 1];
                if (sec == 0) {
                    *(float2*)&g_q[idx] = make_float2(v0, v1);
                } else {
                    uint32_t hh, ll;
                    split2(v0, v1, hh, ll);
                    if (sec == 1) {
                        *(uint32_t*)&g_kh[idx] = hh;
                        *(uint32_t*)&g_kl[idx] = ll;
                    } else {
                        *(uint32_t*)&g_vh[idx] = hh;
                        *(uint32_t*)&g_vl[idx] = ll;
                    }
                }
            }
        }
    }
}

// ---------------------------------------------------------------------------
// proj GEMM: 64x128 tile, cp.async.cg double-buffered (best measured, R12).
// ---------------------------------------------------------------------------
__global__ __launch_bounds__(256) void proj_gemm(float* __restrict__ out) {
    __shared__ __nv_bfloat16 sAh[2][64 * SMP], sAl[2][64 * SMP];
    __shared__ __nv_bfloat16 sBh[2][128 * SMP], sBl[2][128 * SMP];
    const int tid = threadIdx.x;
    const int wid = tid >> 5, lane = tid & 31;
    const int m0 = blockIdx.y * 64, n0 = blockIdx.x * 128;
    const int wm = (wid & 1) * 32;
    const int wn = (wid >> 1) * 32;
    float acc[2][4][4];
    #pragma unroll
    for (int i = 0; i < 2; i++)
        #pragma unroll
        for (int j = 0; j < 4; j++)
            #pragma unroll
            for (int e = 0; e < 4; e++) acc[i][j][e] = 0.0f;
    const int lrow = tid >> 1;
    const int lseg = (tid & 1) * 8;
    const __nv_bfloat16* pah = g_ath + (size_t)(m0 + (lrow & 63)) * CC + lseg;
    const __nv_bfloat16* pal = g_atl + (size_t)(m0 + (lrow & 63)) * CC + lseg;
    const __nv_bfloat16* pbh = gWph + (size_t)(n0 + lrow) * CC + lseg;
    const __nv_bfloat16* pbl = gWpl + (size_t)(n0 + lrow) * CC + lseg;
    const bool doA = (lrow < 64);
    const int soff = lrow * SMP + lseg;
    cp16cg(&sBh[0][soff], pbh);
    cp16cg(&sBl[0][soff], pbl);
    if (doA) {
        cp16cg(&sAh[0][soff], pah);
        cp16cg(&sAl[0][soff], pal);
    }
    CP_COMMIT();
    #pragma unroll 1
    for (int c = 0; c < NCH; c++) {
        const int cur = c & 1, nxt = cur ^ 1;
        if (c + 1 < NCH) {
            int ko = (c + 1) * 16;
            cp16cg(&sBh[nxt][soff], pbh + ko);
            cp16cg(&sBl[nxt][soff], pbl + ko);
            if (doA) {
                cp16cg(&sAh[nxt][soff], pah + ko);
                cp16cg(&sAl[nxt][soff], pal + ko);
            }
            CP_COMMIT();
            CP_WAIT1();
        } else {
            CP_WAIT0();
        }
        __syncthreads();
        uint32_t fbh[4][2], fbl[4][2];
        {
            int br = (lane & 7) + ((lane >> 1) & 8);
            int bc = lane & 8;
            #pragma unroll
            for (int ntp = 0; ntp < 2; ntp++) {
                uint32_t t4[4];
                ldm_x4(t4, &sBh[cur][(wn + ntp * 16 + br) * SMP + bc]);
                fbh[2 * ntp][0] = t4[0]; fbh[2 * ntp][1] = t4[1];
                fbh[2 * ntp + 1][0] = t4[2]; fbh[2 * ntp + 1][1] = t4[3];
                ldm_x4(t4, &sBl[cur][(wn + ntp * 16 + br) * SMP + bc]);
                fbl[2 * ntp][0] = t4[0]; fbl[2 * ntp][1] = t4[1];
                fbl[2 * ntp + 1][0] = t4[2]; fbl[2 * ntp + 1][1] = t4[3];
            }
        }
        {
            int mat = lane >> 3, rr = lane & 7;
            int arow_off = (mat & 1) * 8 + rr;
            int acol = (mat >> 1) * 8;
            #pragma unroll
            for (int mt = 0; mt < 2; mt++) {
                uint32_t fah[4], fal[4];
                int arow = wm + mt * 16 + arow_off;
                ldm_x4(fah, &sAh[cur][arow * SMP + acol]);
                ldm_x4(fal, &sAl[cur][arow * SMP + acol]);
                #pragma unroll
                for (int nt = 0; nt < 4; nt++) {
                    mma_bf16(acc[mt][nt], fah, fbh[nt]);
                    mma_bf16(acc[mt][nt], fah, fbl[nt]);
                    mma_bf16(acc[mt][nt], fal, fbh[nt]);
                }
            }
        }
        __syncthreads();
    }
    #pragma unroll
    for (int mt = 0; mt < 2; mt++) {
        #pragma unroll
        for (int nt = 0; nt < 4; nt++) {
            int n = n0 + wn + nt * 8 + (lane & 3) * 2;
            #pragma unroll
            for (int half = 0; half < 2; half++) {
                int m = m0 + wm + mt * 16 + (lane >> 2) + half * 8;
                float2 v2 = make_float2(acc[mt][nt][half * 2 + 0],
                                        acc[mt][nt][half * 2 + 1]);
                *(float2*)&out[(size_t)m * CC + n] = v2;
            }
        }
    }
}

// ---------------------------------------------------------------------------
// HMMA flash attention (unchanged from R11): Bq=64, Bk=64, cp.async
// split-phase pipeline, base-2 softmax.
// ---------------------------------------------------------------------------
#define ATP 72

__global__ __launch_bounds__(128, 3) void attn_kernel() {
    __shared__ __nv_bfloat16 sKh[64 * ATP], sKl[64 * ATP];
    __shared__ __nv_bfloat16 sVh[64 * ATP], sVl[64 * ATP];

    const int qt = gridDim.x - 1 - blockIdx.x;   // heavy blocks first
    const int bh = blockIdx.y;
    const int q0 = qt * 64;
    const int tid = threadIdx.x;
    const int warp = tid >> 5, lane = tid & 31;
    const size_t base = (size_t)bh * TT * HD;
    const float* qp = g_q + base;

    const int r = lane >> 2;
    const int c2 = (lane & 3) * 2;
    const float QS = 0.125f * 1.44269504088896f;   // 1/sqrt(64) * log2(e)

    const int frow = tid >> 1;          // 0..63
    const int fcb  = (tid & 1) * 32;    // col half

    // ---- prologue: start K(0) and V(0) streams ----
    {
        size_t g = base + (size_t)frow * HD + fcb;
        #pragma unroll
        for (int u = 0; u < 4; u++) {
            cp16(&sKh[frow * ATP + fcb + u * 8], &g_kh[g + u * 8]);
            cp16(&sKl[frow * ATP + fcb + u * 8], &g_kl[g + u * 8]);
        }
        CP_COMMIT();
        #pragma unroll
        for (int u = 0; u < 4; u++) {
            cp16(&sVh[frow * ATP + fcb + u * 8], &g_vh[g + u * 8]);
            cp16(&sVl[frow * ATP + fcb + u * 8], &g_vl[g + u * 8]);
        }
        CP_COMMIT();
    }

    // Q fragments (A-layout, 4 k-chunks over HD=64), hi/lo, from gmem
    uint32_t qfh[4][4], qfl[4][4];
    #pragma unroll
    for (int kc = 0; kc < 4; kc++) {
        #pragma unroll
        for (int e = 0; e < 4; e++) {
            int row = q0 + warp * 16 + r + ((e & 1) ? 8 : 0);
            int col = kc * 16 + c2 + ((e & 2) ? 8 : 0);
            float2 v = *(const float2*)&qp[(size_t)row * HD + col];
            split2(v.x * QS, v.y * QS, qfh[kc][e], qfl[kc][e]);
        }
    }

    float mi[2] = {-1e30f, -1e30f};
    float li[2] = {0.0f, 0.0f};
    float o[8][4];
    #pragma unroll
    for (int nt = 0; nt < 8; nt++)
        #pragma unroll
        for (int e = 0; e < 4; e++) o[nt][e] = 0.0f;

    CP_WAIT1();          // K(0) ready (V(0) may still be in flight)
    __syncthreads();

    for (int kt = 0; kt <= qt; kt++) {
        const int k0 = kt * 64;

        // ---- S = Q @ K^T  (K(kt) resident) ----
        float s[8][4];
        #pragma unroll
        for (int nt = 0; nt < 8; nt++)
            #pragma unroll
            for (int e = 0; e < 4; e++) s[nt][e] = 0.0f;

        {
            int br = (lane & 7) + ((lane >> 1) & 8);
            int bc = lane & 8;
            #pragma unroll
            for (int ntp = 0; ntp < 4; ntp++) {
                #pragma unroll
                for (int kc = 0; kc < 4; kc++) {
                    uint32_t kh4[4], kl4[4];
                    ldm_x4(kh4, &sKh[(ntp * 16 + br) * ATP + kc * 16 + bc]);
                    ldm_x4(kl4, &sKl[(ntp * 16 + br) * ATP + kc * 16 + bc]);
                    mma_bf16(s[2 * ntp],     qfh[kc], kh4);
                    mma_bf16(s[2 * ntp],     qfh[kc], kl4);
                    mma_bf16(s[2 * ntp],     qfl[kc], kh4);
                    mma_bf16(s[2 * ntp + 1], qfh[kc], kh4 + 2);
                    mma_bf16(s[2 * ntp + 1], qfh[kc], kl4 + 2);
                    mma_bf16(s[2 * ntp + 1], qfl[kc], kh4 + 2);
                }
            }
        }
        __syncthreads();   // all warps done reading K(kt)

        // ---- issue K(kt+1) stream (overlaps softmax) ----
        if (kt < qt) {
            size_t g = base + (size_t)(k0 + 64 + frow) * HD + fcb;
            #pragma unroll
            for (int u = 0; u < 4; u++) {
                cp16(&sKh[frow * ATP + fcb + u * 8], &g_kh[g + u * 8]);
                cp16(&sKl[frow * ATP + fcb + u * 8], &g_kl[g + u * 8]);
            }
        }
        CP_COMMIT();

        // ---- causal mask on diagonal tile ----
        if (kt == qt) {
            const int row0 = q0 + warp * 16 + r;
            #pragma unroll
            for (int nt = 0; nt < 8; nt++) {
                int colb = k0 + nt * 8 + c2;
                if (colb     > row0)     s[nt][0] = -1e30f;
                if (colb + 1 > row0)     s[nt][1] = -1e30f;
                if (colb     > row0 + 8) s[nt][2] = -1e30f;
                if (colb + 1 > row0 + 8) s[nt][3] = -1e30f;
            }
        }

        // ---- online softmax (base-2) ----
        #pragma unroll
        for (int h = 0; h < 2; h++) {
            float m = -1e30f;
            #pragma unroll
            for (int nt = 0; nt < 8; nt++)
                m = fmaxf(m, fmaxf(s[nt][h * 2], s[nt][h * 2 + 1]));
            m = fmaxf(m, __shfl_xor_sync(0xffffffffu, m, 1));
            m = fmaxf(m, __shfl_xor_sync(0xffffffffu, m, 2));
            float mnew = fmaxf(mi[h], m);
            float alpha = ex2f(mi[h] - mnew);
            float sum = 0.0f;
            #pragma unroll
            for (int nt = 0; nt < 8; nt++) {
                s[nt][h * 2]     = ex2f(s[nt][h * 2] - mnew);
                s[nt][h * 2 + 1] = ex2f(s[nt][h * 2 + 1] - mnew);
                sum += s[nt][h * 2] + s[nt][h * 2 + 1];
            }
            sum += __shfl_xor_sync(0xffffffffu, sum, 1);
            sum += __shfl_xor_sync(0xffffffffu, sum, 2);
            li[h] = li[h] * alpha + sum;
            mi[h] = mnew;
            #pragma unroll
            for (int nt = 0; nt < 8; nt++) {
                o[nt][h * 2]     *= alpha;
                o[nt][h * 2 + 1] *= alpha;
            }
        }

        // ---- P to A-fragments, hi/lo split (still overlapping K stream) ----
        uint32_t pfh[4][4], pfl[4][4];
        #pragma unroll
        for (int kc = 0; kc < 4; kc++) {
            split2(s[2 * kc][0],     s[2 * kc][1],     pfh[kc][0], pfl[kc][0]);
            split2(s[2 * kc][2],     s[2 * kc][3],     pfh[kc][1], pfl[kc][1]);
            split2(s[2 * kc + 1][0], s[2 * kc + 1][1], pfh[kc][2], pfl[kc][2]);
            split2(s[2 * kc + 1][2], s[2 * kc + 1][3], pfh[kc][3], pfl[kc][3]);
        }

        CP_WAIT1();        // V(kt) ready (K(kt+1) may still be in flight)
        __syncthreads();

        // ---- O += P @ V ----
        {
            const int vr = lane & 15;
            const int vc = (lane >> 4) & 1;
            #pragma unroll
            for (int ntp = 0; ntp < 4; ntp++) {
                #pragma unroll
                for (int kc = 0; kc < 4; kc++) {
                    uint32_t vh4[4], vl4[4];
                    ldm_x4_trans(vh4, &sVh[(kc * 16 + vr) * ATP + (2 * ntp + vc) * 8]);
                    ldm_x4_trans(vl4, &sVl[(kc * 16 + vr) * ATP + (2 * ntp + vc) * 8]);
                    mma_bf16(o[2 * ntp],     pfh[kc], vh4);
                    mma_bf16(o[2 * ntp],     pfh[kc], vl4);
                    mma_bf16(o[2 * ntp],     pfl[kc], vh4);
                    mma_bf16(o[2 * ntp + 1], pfh[kc], vh4 + 2);
                    mma_bf16(o[2 * ntp + 1], pfh[kc], vl4 + 2);
                    mma_bf16(o[2 * ntp + 1], pfl[kc], vh4 + 2);
                }
            }
        }
        __syncthreads();   // all warps done reading V(kt)

        // ---- issue V(kt+1) stream (overlaps next S-MMA) ----
        if (kt < qt) {
            size_t g = base + (size_t)(k0 + 64 + frow) * HD + fcb;
            #pragma unroll
            for (int u = 0; u < 4; u++) {
                cp16(&sVh[frow * ATP + fcb + u * 8], &g_vh[g + u * 8]);
                cp16(&sVl[frow * ATP + fcb + u * 8], &g_vl[g + u * 8]);
            }
        }
        CP_COMMIT();

        CP_WAIT1();        // K(kt+1) ready (V(kt+1) may still be in flight)
        __syncthreads();
    }

    // ---- epilogue: normalize, split, write bf16 hi/lo [B,T,C] ----
    const int b = bh / NH, head = bh % NH;
    #pragma unroll
    for (int h = 0; h < 2; h++) {
        float inv = 1.0f / li[h];
        int row = q0 + warp * 16 + r + h * 8;
        size_t doff = (size_t)(b * TT + row) * CC + head * HD;
        #pragma unroll
        for (int nt = 0; nt < 8; nt++) {
            uint32_t hh, ll;
            split2(o[nt][h * 2] * inv, o[nt][h * 2 + 1] * inv, hh, ll);
            *(uint32_t*)&g_ath[doff + nt * 8 + c2] = hh;
            *(uint32_t*)&g_atl[doff + nt * 8 + c2] = ll;
        }
    }
}

// ---------------------------------------------------------------------------
extern "C" void kernel_launch(void* const* d_in, const int* in_sizes, int n_in,
                              void* d_out, int out_size) {
    const float* x  = (const float*)d_in[0];   // [2,2048,768]
    const float* Wa = (const float*)d_in[1];   // [2304,768]
    const float* Wp = (const float*)d_in[2];   // [768,768]
    float* out = (float*)d_out;                // [2,2048,768]

    __nv_bfloat16 *xh, *xl, *wah, *wal, *wph, *wpl;
    cudaGetSymbolAddress((void**)&xh,  gXh);
    cudaGetSymbolAddress((void**)&xl,  gXl);
    cudaGetSymbolAddress((void**)&wah, gWah);
    cudaGetSymbolAddress((void**)&wal, gWal);
    cudaGetSymbolAddress((void**)&wph, gWph);
    cudaGetSymbolAddress((void**)&wpl, gWpl);

    split_pass<<<(MQ * CC / 4 + 255) / 256, 256>>>(x, xh, xl, MQ * CC / 4);
    split_pass<<<(3 * CC * CC / 4 + 255) / 256, 256>>>(Wa, wah, wal, 3 * CC * CC / 4);
    split_pass<<<(CC * CC / 4 + 255) / 256, 256>>>(Wp, wph, wpl, CC * CC / 4);

    // QKV: M=4096 (32 tiles), N=2304 (18 tiles)
    qkv_gemm<<<dim3(18, 32), 256>>>();

    // Attention: 32 q-tiles (Bq=64) x 24 (b,h)
    attn_kernel<<<dim3(32, 24), 128>>>();

    // Proj: M=4096 (64 tiles of 64), N=768 (6 tiles of 128)
    proj_gemm<<<dim3(6, 64), 256>>>(out);
}

// round 15
// speedup vs baseline: 1.1138x; 1.0760x over previous
#include <cuda_runtime.h>
#include <cuda_bf16.h>
#include <math.h>
#include <stdint.h>

#define BB 2
#define TT 2048
#define CC 768
#define NH 12
#define HD 64
#define MQ (BB*TT)   // 4096

// Scratch (allocation-free rule: __device__ globals)
__device__ float g_q[BB*NH*TT*HD];
__device__ __nv_bfloat16 g_kh[BB*NH*TT*HD], g_kl[BB*NH*TT*HD];
__device__ __nv_bfloat16 g_vh[BB*NH*TT*HD], g_vl[BB*NH*TT*HD];
__device__ __nv_bfloat16 g_ath[(size_t)BB*TT*CC], g_atl[(size_t)BB*TT*CC];
__device__ __nv_bfloat16 gXh[MQ*CC],     gXl[MQ*CC];
__device__ __nv_bfloat16 gWah[3*CC*CC],  gWal[3*CC*CC];
__device__ __nv_bfloat16 gWph[CC*CC],    gWpl[CC*CC];

// ---------------------------------------------------------------------------
// helpers
// ---------------------------------------------------------------------------
__device__ __forceinline__ void mma_bf16(float* d, const uint32_t* a,
                                         const uint32_t* b) {
    asm volatile(
        "mma.sync.aligned.m16n8k16.row.col.f32.bf16.bf16.f32 "
        "{%0,%1,%2,%3}, {%4,%5,%6,%7}, {%8,%9}, {%0,%1,%2,%3};"
        : "+f"(d[0]), "+f"(d[1]), "+f"(d[2]), "+f"(d[3])
        : "r"(a[0]), "r"(a[1]), "r"(a[2]), "r"(a[3]), "r"(b[0]), "r"(b[1]));
}

__device__ __forceinline__ void ldm_x4(uint32_t* r, const void* p) {
    uint32_t addr = (uint32_t)__cvta_generic_to_shared(p);
    asm volatile("ldmatrix.sync.aligned.m8n8.x4.shared.b16 {%0,%1,%2,%3}, [%4];"
                 : "=r"(r[0]), "=r"(r[1]), "=r"(r[2]), "=r"(r[3]) : "r"(addr));
}

__device__ __forceinline__ void ldm_x4_trans(uint32_t* r, const void* p) {
    uint32_t addr = (uint32_t)__cvta_generic_to_shared(p);
    asm volatile("ldmatrix.sync.aligned.m8n8.x4.trans.shared.b16 {%0,%1,%2,%3}, [%4];"
                 : "=r"(r[0]), "=r"(r[1]), "=r"(r[2]), "=r"(r[3]) : "r"(addr));
}

__device__ __forceinline__ float ex2f(float x) {
    float y;
    asm("ex2.approx.f32 %0, %1;" : "=f"(y) : "f"(x));
    return y;
}

__device__ __forceinline__ void cp16(void* smem, const void* gmem) {
    uint32_t a = (uint32_t)__cvta_generic_to_shared(smem);
    asm volatile("cp.async.ca.shared.global [%0], [%1], 16;" :: "r"(a), "l"(gmem));
}
__device__ __forceinline__ void cp16cg(void* smem, const void* gmem) {
    uint32_t a = (uint32_t)__cvta_generic_to_shared(smem);
    asm volatile("cp.async.cg.shared.global [%0], [%1], 16;" :: "r"(a), "l"(gmem));
}
#define CP_COMMIT() asm volatile("cp.async.commit_group;" ::: "memory")
#define CP_WAIT0()  asm volatile("cp.async.wait_group 0;" ::: "memory")
#define CP_WAIT1()  asm volatile("cp.async.wait_group 1;" ::: "memory")

// Split (x,y) into packed bf16x2 hi and lo (x in low half)
__device__ __forceinline__ void split2(float x, float y, uint32_t& hi, uint32_t& lo) {
    __nv_bfloat16 hx = __float2bfloat16_rn(x);
    __nv_bfloat16 hy = __float2bfloat16_rn(y);
    __nv_bfloat162 h2(hx, hy);
    __nv_bfloat162 l2(__float2bfloat16_rn(x - __bfloat162float(hx)),
                      __float2bfloat16_rn(y - __bfloat162float(hy)));
    hi = *(uint32_t*)&h2;
    lo = *(uint32_t*)&l2;
}

// ---------------------------------------------------------------------------
// Pre-pass: split fp32 -> bf16 hi/lo
// ---------------------------------------------------------------------------
__global__ __launch_bounds__(256) void split_pass(const float* __restrict__ src,
                                                  __nv_bfloat16* __restrict__ dh,
                                                  __nv_bfloat16* __restrict__ dl,
                                                  int n4) {
    int i = blockIdx.x * 256 + threadIdx.x;
    if (i < n4) {
        float4 v = ((const float4*)src)[i];
        uint32_t h0, l0, h1, l1;
        split2(v.x, v.y, h0, l0);
        split2(v.z, v.w, h1, l1);
        ((uint32_t*)dh)[i * 2]     = h0;
        ((uint32_t*)dh)[i * 2 + 1] = h1;
        ((uint32_t*)dl)[i * 2]     = l0;
        ((uint32_t*)dl)[i * 2 + 1] = l1;
    }
}

// ---------------------------------------------------------------------------
// qkv GEMM: 128x128 tile, register-prefetch double-buffered smem (best
// measured, R9/R13).
// ---------------------------------------------------------------------------
#define SMP 24
#define NCH (CC / 16)   // 48 chunks

__global__ __launch_bounds__(256) void qkv_gemm() {
    __shared__ __nv_bfloat16 sAh[2][128 * SMP], sAl[2][128 * SMP];
    __shared__ __nv_bfloat16 sBh[2][128 * SMP], sBl[2][128 * SMP];
    const int tid = threadIdx.x;
    const int wid = tid >> 5, lane = tid & 31;
    const int m0 = blockIdx.y * 128, n0 = blockIdx.x * 128;
    const int wm = (wid & 1) * 64;
    const int wn = (wid >> 1) * 32;
    float acc[4][4][4];
    #pragma unroll
    for (int i = 0; i < 4; i++)
        #pragma unroll
        for (int j = 0; j < 4; j++)
            #pragma unroll
            for (int e = 0; e < 4; e++) acc[i][j][e] = 0.0f;
    const int lrow = tid >> 1;
    const int lseg = (tid & 1) * 8;
    const __nv_bfloat16* pah = gXh  + (size_t)(m0 + lrow) * CC + lseg;
    const __nv_bfloat16* pal = gXl  + (size_t)(m0 + lrow) * CC + lseg;
    const __nv_bfloat16* pbh = gWah + (size_t)(n0 + lrow) * CC + lseg;
    const __nv_bfloat16* pbl = gWal + (size_t)(n0 + lrow) * CC + lseg;
    const int soff = lrow * SMP + lseg;
    {
        uint4 a0 = *(const uint4*)pah;
        uint4 a1 = *(const uint4*)pal;
        uint4 b0 = *(const uint4*)pbh;
        uint4 b1 = *(const uint4*)pbl;
        *(uint4*)&sAh[0][soff] = a0;
        *(uint4*)&sAl[0][soff] = a1;
        *(uint4*)&sBh[0][soff] = b0;
        *(uint4*)&sBl[0][soff] = b1;
    }
    __syncthreads();
    #pragma unroll 1
    for (int c = 0; c < NCH; c++) {
        const int cur = c & 1, nxt = cur ^ 1;
        uint4 rah, ral, rbh, rbl;
        if (c + 1 < NCH) {
            int ko = (c + 1) * 16;
            rah = *(const uint4*)(pah + ko);
            ral = *(const uint4*)(pal + ko);
            rbh = *(const uint4*)(pbh + ko);
            rbl = *(const uint4*)(pbl + ko);
        }
        uint32_t fbh[4][2], fbl[4][2];
        {
            int br = (lane & 7) + ((lane >> 1) & 8);
            int bc = lane & 8;
            #pragma unroll
            for (int ntp = 0; ntp < 2; ntp++) {
                uint32_t t4[4];
                ldm_x4(t4, &sBh[cur][(wn + ntp * 16 + br) * SMP + bc]);
                fbh[2 * ntp][0] = t4[0]; fbh[2 * ntp][1] = t4[1];
                fbh[2 * ntp + 1][0] = t4[2]; fbh[2 * ntp + 1][1] = t4[3];
                ldm_x4(t4, &sBl[cur][(wn + ntp * 16 + br) * SMP + bc]);
                fbl[2 * ntp][0] = t4[0]; fbl[2 * ntp][1] = t4[1];
                fbl[2 * ntp + 1][0] = t4[2]; fbl[2 * ntp + 1][1] = t4[3];
            }
        }
        {
            int mat = lane >> 3, rr = lane & 7;
            int arow_off = (mat & 1) * 8 + rr;
            int acol = (mat >> 1) * 8;
            #pragma unroll
            for (int mt = 0; mt < 4; mt++) {
                uint32_t fah[4], fal[4];
                int arow = wm + mt * 16 + arow_off;
                ldm_x4(fah, &sAh[cur][arow * SMP + acol]);
                ldm_x4(fal, &sAl[cur][arow * SMP + acol]);
                #pragma unroll
                for (int nt = 0; nt < 4; nt++) {
                    mma_bf16(acc[mt][nt], fah, fbh[nt]);
                    mma_bf16(acc[mt][nt], fah, fbl[nt]);
                    mma_bf16(acc[mt][nt], fal, fbh[nt]);
                }
            }
        }
        if (c + 1 < NCH) {
            *(uint4*)&sAh[nxt][soff] = rah;
            *(uint4*)&sAl[nxt][soff] = ral;
            *(uint4*)&sBh[nxt][soff] = rbh;
            *(uint4*)&sBl[nxt][soff] = rbl;
        }
        __syncthreads();
    }
    // epilogue: Q -> fp32 g_q; K,V -> bf16 hi/lo, all [B,H,T,D]
    #pragma unroll
    for (int mt = 0; mt < 4; mt++) {
        #pragma unroll
        for (int nt = 0; nt < 4; nt++) {
            int n = n0 + wn + nt * 8 + (lane & 3) * 2;
            int sec = n / CC;               // 0=q 1=k 2=v
            int c2 = n - sec * CC;
            int h = c2 >> 6, d = c2 & 63;
            #pragma unroll
            for (int half = 0; half < 2; half++) {
                int m = m0 + wm + mt * 16 + (lane >> 2) + half * 8;
                int b = m >> 11, t = m & 2047;
                size_t idx = (size_t)((b * NH + h) * TT + t) * HD + d;
                float v0 = acc[mt][nt][half * 2 + 0];
                float v1 = acc[mt][nt][half * 2 + 1];
                if (sec == 0) {
                    *(float2*)&g_q[idx] = make_float2(v0, v1);
                } else {
                    uint32_t hh, ll;
                    split2(v0, v1, hh, ll);
                    if (sec == 1) {
                        *(uint32_t*)&g_kh[idx] = hh;
                        *(uint32_t*)&g_kl[idx] = ll;
                    } else {
                        *(uint32_t*)&g_vh[idx] = hh;
                        *(uint32_t*)&g_vl[idx] = ll;
                    }
                }
            }
        }
    }
}

// ---------------------------------------------------------------------------
// proj GEMM: 64x128 tile, cp.async.cg double-buffered (best measured, R12).
// ---------------------------------------------------------------------------
__global__ __launch_bounds__(256) void proj_gemm(float* __restrict__ out) {
    __shared__ __nv_bfloat16 sAh[2][64 * SMP], sAl[2][64 * SMP];
    __shared__ __nv_bfloat16 sBh[2][128 * SMP], sBl[2][128 * SMP];
    const int tid = threadIdx.x;
    const int wid = tid >> 5, lane = tid & 31;
    const int m0 = blockIdx.y * 64, n0 = blockIdx.x * 128;
    const int wm = (wid & 1) * 32;
    const int wn = (wid >> 1) * 32;
    float acc[2][4][4];
    #pragma unroll
    for (int i = 0; i < 2; i++)
        #pragma unroll
        for (int j = 0; j < 4; j++)
            #pragma unroll
            for (int e = 0; e < 4; e++) acc[i][j][e] = 0.0f;
    const int lrow = tid >> 1;
    const int lseg = (tid & 1) * 8;
    const __nv_bfloat16* pah = g_ath + (size_t)(m0 + (lrow & 63)) * CC + lseg;
    const __nv_bfloat16* pal = g_atl + (size_t)(m0 + (lrow & 63)) * CC + lseg;
    const __nv_bfloat16* pbh = gWph + (size_t)(n0 + lrow) * CC + lseg;
    const __nv_bfloat16* pbl = gWpl + (size_t)(n0 + lrow) * CC + lseg;
    const bool doA = (lrow < 64);
    const int soff = lrow * SMP + lseg;
    cp16cg(&sBh[0][soff], pbh);
    cp16cg(&sBl[0][soff], pbl);
    if (doA) {
        cp16cg(&sAh[0][soff], pah);
        cp16cg(&sAl[0][soff], pal);
    }
    CP_COMMIT();
    #pragma unroll 1
    for (int c = 0; c < NCH; c++) {
        const int cur = c & 1, nxt = cur ^ 1;
        if (c + 1 < NCH) {
            int ko = (c + 1) * 16;
            cp16cg(&sBh[nxt][soff], pbh + ko);
            cp16cg(&sBl[nxt][soff], pbl + ko);
            if (doA) {
                cp16cg(&sAh[nxt][soff], pah + ko);
                cp16cg(&sAl[nxt][soff], pal + ko);
            }
            CP_COMMIT();
            CP_WAIT1();
        } else {
            CP_WAIT0();
        }
        __syncthreads();
        uint32_t fbh[4][2], fbl[4][2];
        {
            int br = (lane & 7) + ((lane >> 1) & 8);
            int bc = lane & 8;
            #pragma unroll
            for (int ntp = 0; ntp < 2; ntp++) {
                uint32_t t4[4];
                ldm_x4(t4, &sBh[cur][(wn + ntp * 16 + br) * SMP + bc]);
                fbh[2 * ntp][0] = t4[0]; fbh[2 * ntp][1] = t4[1];
                fbh[2 * ntp + 1][0] = t4[2]; fbh[2 * ntp + 1][1] = t4[3];
                ldm_x4(t4, &sBl[cur][(wn + ntp * 16 + br) * SMP + bc]);
                fbl[2 * ntp][0] = t4[0]; fbl[2 * ntp][1] = t4[1];
                fbl[2 * ntp + 1][0] = t4[2]; fbl[2 * ntp + 1][1] = t4[3];
            }
        }
        {
            int mat = lane >> 3, rr = lane & 7;
            int arow_off = (mat & 1) * 8 + rr;
            int acol = (mat >> 1) * 8;
            #pragma unroll
            for (int mt = 0; mt < 2; mt++) {
                uint32_t fah[4], fal[4];
                int arow = wm + mt * 16 + arow_off;
                ldm_x4(fah, &sAh[cur][arow * SMP + acol]);
                ldm_x4(fal, &sAl[cur][arow * SMP + acol]);
                #pragma unroll
                for (int nt = 0; nt < 4; nt++) {
                    mma_bf16(acc[mt][nt], fah, fbh[nt]);
                    mma_bf16(acc[mt][nt], fah, fbl[nt]);
                    mma_bf16(acc[mt][nt], fal, fbh[nt]);
                }
            }
        }
        __syncthreads();
    }
    #pragma unroll
    for (int mt = 0; mt < 2; mt++) {
        #pragma unroll
        for (int nt = 0; nt < 4; nt++) {
            int n = n0 + wn + nt * 8 + (lane & 3) * 2;
            #pragma unroll
            for (int half = 0; half < 2; half++) {
                int m = m0 + wm + mt * 16 + (lane >> 2) + half * 8;
                float2 v2 = make_float2(acc[mt][nt][half * 2 + 0],
                                        acc[mt][nt][half * 2 + 1]);
                *(float2*)&out[(size_t)m * CC + n] = v2;
            }
        }
    }
}

// ---------------------------------------------------------------------------
// HMMA flash attention: Bq=64 (4 warps x 16 rows), Bk=32 with FULL
// double-buffered K/V (2 stages x 4 arrays x 32x72 bf16 = 36.9KB). One
// wait+sync per 32-key tile; cp for tile kt+1 hides under tile kt compute.
// ---------------------------------------------------------------------------
#define ATP 72

__global__ __launch_bounds__(128, 4) void attn_kernel() {
    __shared__ __nv_bfloat16 sKh[2][32 * ATP], sKl[2][32 * ATP];
    __shared__ __nv_bfloat16 sVh[2][32 * ATP], sVl[2][32 * ATP];

    const int qt = gridDim.x - 1 - blockIdx.x;   // heavy blocks first
    const int bh = blockIdx.y;
    const int q0 = qt * 64;
    const int tid = threadIdx.x;
    const int warp = tid >> 5, lane = tid & 31;
    const size_t base = (size_t)bh * TT * HD;
    const float* qp = g_q + base;

    const int r = lane >> 2;
    const int c2 = (lane & 3) * 2;
    const float QS = 0.125f * 1.44269504088896f;   // 1/sqrt(64) * log2(e)
    const int wrow0 = q0 + warp * 16;

    const int frow = tid >> 2;          // 0..31
    const int fcb  = (tid & 3) * 16;    // col quarter

    // ---- prologue: fill stage 0 with tile 0 ----
    {
        size_t g = base + (size_t)frow * HD + fcb;
        cp16(&sKh[0][frow * ATP + fcb],     &g_kh[g]);
        cp16(&sKh[0][frow * ATP + fcb + 8], &g_kh[g + 8]);
        cp16(&sKl[0][frow * ATP + fcb],     &g_kl[g]);
        cp16(&sKl[0][frow * ATP + fcb + 8], &g_kl[g + 8]);
        cp16(&sVh[0][frow * ATP + fcb],     &g_vh[g]);
        cp16(&sVh[0][frow * ATP + fcb + 8], &g_vh[g + 8]);
        cp16(&sVl[0][frow * ATP + fcb],     &g_vl[g]);
        cp16(&sVl[0][frow * ATP + fcb + 8], &g_vl[g + 8]);
        CP_COMMIT();
    }

    // Q fragments (A-layout, 4 k-chunks over HD=64), hi/lo, from gmem
    uint32_t qfh[4][4], qfl[4][4];
    #pragma unroll
    for (int kc = 0; kc < 4; kc++) {
        #pragma unroll
        for (int e = 0; e < 4; e++) {
            int row = wrow0 + r + ((e & 1) ? 8 : 0);
            int col = kc * 16 + c2 + ((e & 2) ? 8 : 0);
            float2 v = *(const float2*)&qp[(size_t)row * HD + col];
            split2(v.x * QS, v.y * QS, qfh[kc][e], qfl[kc][e]);
        }
    }

    float mi[2] = {-1e30f, -1e30f};
    float li[2] = {0.0f, 0.0f};
    float o[8][4];
    #pragma unroll
    for (int nt = 0; nt < 8; nt++)
        #pragma unroll
        for (int e = 0; e < 4; e++) o[nt][e] = 0.0f;

    const int nkt = 2 * qt + 2;   // 32-key tiles covering keys <= q0+63
    for (int kt = 0; kt < nkt; kt++) {
        const int k0 = kt * 32;
        const int cur = kt & 1, nxt = cur ^ 1;

        CP_WAIT0();        // tile kt resident in buf cur
        __syncthreads();   // all warps past previous reads of buf nxt

        // ---- issue tile kt+1 into the other buffer (hides under compute) --
        if (kt + 1 < nkt) {
            size_t g = base + (size_t)(k0 + 32 + frow) * HD + fcb;
            cp16(&sKh[nxt][frow * ATP + fcb],     &g_kh[g]);
            cp16(&sKh[nxt][frow * ATP + fcb + 8], &g_kh[g + 8]);
            cp16(&sKl[nxt][frow * ATP + fcb],     &g_kl[g]);
            cp16(&sKl[nxt][frow * ATP + fcb + 8], &g_kl[g + 8]);
            cp16(&sVh[nxt][frow * ATP + fcb],     &g_vh[g]);
            cp16(&sVh[nxt][frow * ATP + fcb + 8], &g_vh[g + 8]);
            cp16(&sVl[nxt][frow * ATP + fcb],     &g_vl[g]);
            cp16(&sVl[nxt][frow * ATP + fcb + 8], &g_vl[g + 8]);
        }
        CP_COMMIT();

        // ---- S = Q @ K^T (32 keys: 2 n-tile-pairs x 4 d-chunks x 3 terms) --
        float s[4][4];
        #pragma unroll
        for (int nt = 0; nt < 4; nt++)
            #pragma unroll
            for (int e = 0; e < 4; e++) s[nt][e] = 0.0f;

        {
            int br = (lane & 7) + ((lane >> 1) & 8);
            int bc = lane & 8;
            #pragma unroll
            for (int ntp = 0; ntp < 2; ntp++) {
                #pragma unroll
                for (int kc = 0; kc < 4; kc++) {
                    uint32_t kh4[4], kl4[4];
                    ldm_x4(kh4, &sKh[cur][(ntp * 16 + br) * ATP + kc * 16 + bc]);
                    ldm_x4(kl4, &sKl[cur][(ntp * 16 + br) * ATP + kc * 16 + bc]);
                    mma_bf16(s[2 * ntp],     qfh[kc], kh4);
                    mma_bf16(s[2 * ntp],     qfh[kc], kl4);
                    mma_bf16(s[2 * ntp],     qfl[kc], kh4);
                    mma_bf16(s[2 * ntp + 1], qfh[kc], kh4 + 2);
                    mma_bf16(s[2 * ntp + 1], qfh[kc], kl4 + 2);
                    mma_bf16(s[2 * ntp + 1], qfl[kc], kh4 + 2);
                }
            }
        }

        // ---- causal mask (tiles overlapping this warp's diagonal) ----
        if (k0 + 31 > wrow0) {
            #pragma unroll
            for (int nt = 0; nt < 4; nt++) {
                int colb = k0 + nt * 8 + c2;
                int row0 = wrow0 + r;
                if (colb     > row0)     s[nt][0] = -1e30f;
                if (colb + 1 > row0)     s[nt][1] = -1e30f;
                if (colb     > row0 + 8) s[nt][2] = -1e30f;
                if (colb + 1 > row0 + 8) s[nt][3] = -1e30f;
            }
        }

        // ---- online softmax (base-2) ----
        #pragma unroll
        for (int h = 0; h < 2; h++) {
            float m = -1e30f;
            #pragma unroll
            for (int nt = 0; nt < 4; nt++)
                m = fmaxf(m, fmaxf(s[nt][h * 2], s[nt][h * 2 + 1]));
            m = fmaxf(m, __shfl_xor_sync(0xffffffffu, m, 1));
            m = fmaxf(m, __shfl_xor_sync(0xffffffffu, m, 2));
            float mnew = fmaxf(mi[h], m);
            float alpha = ex2f(mi[h] - mnew);
            float sum = 0.0f;
            #pragma unroll
            for (int nt = 0; nt < 4; nt++) {
                s[nt][h * 2]     = ex2f(s[nt][h * 2] - mnew);
                s[nt][h * 2 + 1] = ex2f(s[nt][h * 2 + 1] - mnew);
                sum += s[nt][h * 2] + s[nt][h * 2 + 1];
            }
            sum += __shfl_xor_sync(0xffffffffu, sum, 1);
            sum += __shfl_xor_sync(0xffffffffu, sum, 2);
            li[h] = li[h] * alpha + sum;
            mi[h] = mnew;
            #pragma unroll
            for (int nt = 0; nt < 8; nt++) {
                o[nt][h * 2]     *= alpha;
                o[nt][h * 2 + 1] *= alpha;
            }
        }

        // ---- P to A-fragments (2 key-chunks), hi/lo split ----
        uint32_t pfh[2][4], pfl[2][4];
        #pragma unroll
        for (int kc = 0; kc < 2; kc++) {
            split2(s[2 * kc][0],     s[2 * kc][1],     pfh[kc][0], pfl[kc][0]);
            split2(s[2 * kc][2],     s[2 * kc][3],     pfh[kc][1], pfl[kc][1]);
            split2(s[2 * kc + 1][0], s[2 * kc + 1][1], pfh[kc][2], pfl[kc][2]);
            split2(s[2 * kc + 1][2], s[2 * kc + 1][3], pfh[kc][3], pfl[kc][3]);
        }

        // ---- O += P @ V (8 d n-tiles x 2 key-chunks x 3 terms) ----
        {
            const int vr = lane & 15;
            const int vc = (lane >> 4) & 1;
            #pragma unroll
            for (int ntp = 0; ntp < 4; ntp++) {
                #pragma unroll
                for (int kc = 0; kc < 2; kc++) {
                    uint32_t vh4[4], vl4[4];
                    ldm_x4_trans(vh4, &sVh[cur][(kc * 16 + vr) * ATP + (2 * ntp + vc) * 8]);
                    ldm_x4_trans(vl4, &sVl[cur][(kc * 16 + vr) * ATP + (2 * ntp + vc) * 8]);
                    mma_bf16(o[2 * ntp],     pfh[kc], vh4);
                    mma_bf16(o[2 * ntp],     pfh[kc], vl4);
                    mma_bf16(o[2 * ntp],     pfl[kc], vh4);
                    mma_bf16(o[2 * ntp + 1], pfh[kc], vh4 + 2);
                    mma_bf16(o[2 * ntp + 1], pfh[kc], vl4 + 2);
                    mma_bf16(o[2 * ntp + 1], pfl[kc], vh4 + 2);
                }
            }
        }
    }

    // ---- epilogue: normalize, split, write bf16 hi/lo [B,T,C] ----
    const int b = bh / NH, head = bh % NH;
    #pragma unroll
    for (int h = 0; h < 2; h++) {
        float inv = 1.0f / li[h];
        int row = wrow0 + r + h * 8;
        size_t doff = (size_t)(b * TT + row) * CC + head * HD;
        #pragma unroll
        for (int nt = 0; nt < 8; nt++) {
            uint32_t hh, ll;
            split2(o[nt][h * 2] * inv, o[nt][h * 2 + 1] * inv, hh, ll);
            *(uint32_t*)&g_ath[doff + nt * 8 + c2] = hh;
            *(uint32_t*)&g_atl[doff + nt * 8 + c2] = ll;
        }
    }
}

// ---------------------------------------------------------------------------
extern "C" void kernel_launch(void* const* d_in, const int* in_sizes, int n_in,
                              void* d_out, int out_size) {
    const float* x  = (const float*)d_in[0];   // [2,2048,768]
    const float* Wa = (const float*)d_in[1];   // [2304,768]
    const float* Wp = (const float*)d_in[2];   // [768,768]
    float* out = (float*)d_out;                // [2,2048,768]

    __nv_bfloat16 *xh, *xl, *wah, *wal, *wph, *wpl;
    cudaGetSymbolAddress((void**)&xh,  gXh);
    cudaGetSymbolAddress((void**)&xl,  gXl);
    cudaGetSymbolAddress((void**)&wah, gWah);
    cudaGetSymbolAddress((void**)&wal, gWal);
    cudaGetSymbolAddress((void**)&wph, gWph);
    cudaGetSymbolAddress((void**)&wpl, gWpl);

    split_pass<<<(MQ * CC / 4 + 255) / 256, 256>>>(x, xh, xl, MQ * CC / 4);
    split_pass<<<(3 * CC * CC / 4 + 255) / 256, 256>>>(Wa, wah, wal, 3 * CC * CC / 4);
    split_pass<<<(CC * CC / 4 + 255) / 256, 256>>>(Wp, wph, wpl, CC * CC / 4);

    // QKV: M=4096 (32 tiles), N=2304 (18 tiles)
    qkv_gemm<<<dim3(18, 32), 256>>>();

    // Attention: 32 q-tiles (Bq=64) x 24 (b,h)
    attn_kernel<<<dim3(32, 24), 128>>>();

    // Proj: M=4096 (64 tiles of 64), N=768 (6 tiles of 128)
    proj_gemm<<<dim3(6, 64), 256>>>(out);
}